// round 1
// baseline (speedup 1.0000x reference)
#include <cuda_runtime.h>

#define EMBED 2048
#define HD    128
#define NB    4
#define SEQ   2048

// Scratch: Q^T and K^T stored [b][d][s] (so the attention kernel loads them
// coalesced straight into k-major smem tiles, no in-kernel transpose);
// V stored [b][s][d].
__device__ float g_qT[NB * HD * SEQ];
__device__ float g_kT[NB * HD * SEQ];
__device__ float g_v [NB * SEQ * HD];

// ---------------------------------------------------------------------------
// Kernel 1: QKV projection. C = X[8192,2048] @ W[2048,128] + bias.
// grid = (8192/64, 3). BM=64, BN=128, BK=16, 256 threads, 4x8 microtile.
// wsel (blockIdx.y) selects Wq/Wk/Wv; q,k epilogues write transposed.
// ---------------------------------------------------------------------------
__global__ __launch_bounds__(256)
void qkv_kernel(const float* __restrict__ X,
                const float* __restrict__ Wq, const float* __restrict__ bq,
                const float* __restrict__ Wk, const float* __restrict__ bk,
                const float* __restrict__ Wv, const float* __restrict__ bv)
{
    __shared__ float As[16][68];    // A stored k-major (transposed on store)
    __shared__ float Bs[16][132];

    const int wsel = blockIdx.y;
    const float* __restrict__ W    = (wsel == 0) ? Wq : (wsel == 1 ? Wk : Wv);
    const float* __restrict__ bias = (wsel == 0) ? bq : (wsel == 1 ? bk : bv);
    const int m0 = blockIdx.x * 64;

    const int t  = threadIdx.x;
    const int tr = t >> 4;          // 0..15  -> rows tr*4..tr*4+3
    const int tc = t & 15;          // 0..15  -> cols tc*4 and 64+tc*4

    const int am  = t >> 2;         // 0..63 : A-tile row
    const int ak  = t & 3;          // float4 slot along k
    const int bk_ = t >> 5;         // 0..7  : B-tile k row (and +8)
    const int bn  = t & 31;         // float4 slot along n

    float acc[4][8];
    #pragma unroll
    for (int i = 0; i < 4; i++)
        #pragma unroll
        for (int j = 0; j < 8; j++) acc[i][j] = 0.f;

    float4 aR  = *(const float4*)(X + (size_t)(m0 + am) * EMBED + ak * 4);
    float4 bR0 = *(const float4*)(W + bk_ * HD + bn * 4);
    float4 bR1 = *(const float4*)(W + (bk_ + 8) * HD + bn * 4);

    for (int kt = 0; kt < EMBED / 16; ++kt) {
        // stage current tile
        As[ak * 4 + 0][am] = aR.x;
        As[ak * 4 + 1][am] = aR.y;
        As[ak * 4 + 2][am] = aR.z;
        As[ak * 4 + 3][am] = aR.w;
        *(float4*)&Bs[bk_][bn * 4]     = bR0;
        *(float4*)&Bs[bk_ + 8][bn * 4] = bR1;
        __syncthreads();
        // prefetch next tile into registers (hidden under the FMA loop)
        if (kt + 1 < EMBED / 16) {
            const int kb = (kt + 1) * 16;
            aR  = *(const float4*)(X + (size_t)(m0 + am) * EMBED + kb + ak * 4);
            bR0 = *(const float4*)(W + (size_t)(kb + bk_) * HD + bn * 4);
            bR1 = *(const float4*)(W + (size_t)(kb + bk_ + 8) * HD + bn * 4);
        }
        #pragma unroll
        for (int kk = 0; kk < 16; ++kk) {
            float4 a  = *(float4*)&As[kk][tr * 4];
            float4 b0 = *(float4*)&Bs[kk][tc * 4];
            float4 b1 = *(float4*)&Bs[kk][64 + tc * 4];
            float av[4]  = {a.x, a.y, a.z, a.w};
            float bv_[8] = {b0.x, b0.y, b0.z, b0.w, b1.x, b1.y, b1.z, b1.w};
            #pragma unroll
            for (int i = 0; i < 4; i++)
                #pragma unroll
                for (int j = 0; j < 8; j++)
                    acc[i][j] += av[i] * bv_[j];
        }
        __syncthreads();
    }

    // bias
    float bb[8];
    #pragma unroll
    for (int jh = 0; jh < 2; jh++)
        #pragma unroll
        for (int j = 0; j < 4; j++) bb[jh * 4 + j] = bias[jh * 64 + tc * 4 + j];
    #pragma unroll
    for (int i = 0; i < 4; i++)
        #pragma unroll
        for (int j = 0; j < 8; j++) acc[i][j] += bb[j];

    const int batch = m0 / SEQ;     // 64 | 2048 so tiles never straddle batches
    const int s0    = m0 % SEQ;

    if (wsel < 2) {
        // transposed epilogue: [d][s], float4 along s
        float* dst = (wsel == 0 ? g_qT : g_kT) + (size_t)batch * HD * SEQ;
        #pragma unroll
        for (int jh = 0; jh < 2; jh++)
            #pragma unroll
            for (int j = 0; j < 4; j++) {
                int n = jh * 64 + tc * 4 + j;
                float4 v = make_float4(acc[0][jh * 4 + j], acc[1][jh * 4 + j],
                                       acc[2][jh * 4 + j], acc[3][jh * 4 + j]);
                *(float4*)(dst + (size_t)n * SEQ + s0 + tr * 4) = v;
            }
    } else {
        float* dst = g_v + (size_t)batch * SEQ * HD;
        #pragma unroll
        for (int i = 0; i < 4; i++) {
            int row = s0 + tr * 4 + i;
            *(float4*)(dst + (size_t)row * HD + tc * 4) =
                make_float4(acc[i][0], acc[i][1], acc[i][2], acc[i][3]);
            *(float4*)(dst + (size_t)row * HD + 64 + tc * 4) =
                make_float4(acc[i][4], acc[i][5], acc[i][6], acc[i][7]);
        }
    }
}

// ---------------------------------------------------------------------------
// Kernel 2: causal flash attention, fp32, online softmax.
// grid = (32, 4): (query tile of 64 rows, batch). 256 threads.
// Dynamic smem: Qs[128][68] (k-major), Ks[128][68], Vs[64][132], Ps[64][68],
//               m/l/alpha rows.
// ---------------------------------------------------------------------------
#define ATTN_SMEM_FLOATS (128*68 + 128*68 + 64*132 + 64*68 + 3*64)

__global__ __launch_bounds__(256)
void attn_kernel(float* __restrict__ out)
{
    extern __shared__ float smem[];
    float (*Qs)[68]  = (float (*)[68])(smem);
    float (*Ks)[68]  = (float (*)[68])(smem + 128 * 68);
    float (*Vs)[132] = (float (*)[132])(smem + 2 * 128 * 68);
    float (*Ps)[68]  = (float (*)[68])(smem + 2 * 128 * 68 + 64 * 132);
    float* m_s  = smem + 2 * 128 * 68 + 64 * 132 + 64 * 68;
    float* l_s  = m_s + 64;
    float* al_s = l_s + 64;

    const int qt = blockIdx.x;
    const int b  = blockIdx.y;
    const int q0 = qt * 64;
    const int t  = threadIdx.x;

    const float* __restrict__ qT = g_qT + (size_t)b * HD * SEQ;
    const float* __restrict__ kT = g_kT + (size_t)b * HD * SEQ;
    const float* __restrict__ vP = g_v  + (size_t)b * SEQ * HD;

    // load Q tile: gmem already [d][s] -> coalesced rows of 64 floats
    #pragma unroll
    for (int l = 0; l < 8; ++l) {
        int idx = t + l * 256;              // 0..2047
        int d = idx >> 4, sq = idx & 15;
        *(float4*)&Qs[d][sq * 4] =
            *(const float4*)(qT + (size_t)d * SEQ + q0 + sq * 4);
    }
    if (t < 64) { m_s[t] = -1e30f; l_s[t] = 0.f; }

    float acc[32];
    #pragma unroll
    for (int c = 0; c < 32; c++) acc[c] = 0.f;

    const int rb = t >> 2;                  // phase-B row (0..63)
    const int cg = t & 3;                   // phase-B col group
    const int tr = t >> 4, tc = t & 15;     // phase-A 16x16 thread grid
    const int r0 = tr * 4, c0 = tc * 4;
    const float RSC = 0.08838834764831845f; // 1/sqrt(128)

    __syncthreads();

    for (int j = 0; j <= qt; ++j) {
        const int k0 = j * 64;
        #pragma unroll
        for (int l = 0; l < 8; ++l) {
            int idx = t + l * 256;
            int d = idx >> 4, sq = idx & 15;
            *(float4*)&Ks[d][sq * 4] =
                *(const float4*)(kT + (size_t)d * SEQ + k0 + sq * 4);
        }
        #pragma unroll
        for (int l = 0; l < 8; ++l) {
            int idx = t + l * 256;
            int s = idx >> 5, cq = idx & 31;
            *(float4*)&Vs[s][cq * 4] =
                *(const float4*)(vP + (size_t)(k0 + s) * HD + cq * 4);
        }
        __syncthreads();

        // ---- phase A: S = Q K^T (64x64), scale, causal mask, online softmax
        float sc[4][4];
        #pragma unroll
        for (int i = 0; i < 4; i++)
            #pragma unroll
            for (int jj = 0; jj < 4; jj++) sc[i][jj] = 0.f;
        for (int k = 0; k < 128; ++k) {
            float4 a  = *(float4*)&Qs[k][r0];
            float4 bb = *(float4*)&Ks[k][c0];
            float av[4]  = {a.x, a.y, a.z, a.w};
            float bv_[4] = {bb.x, bb.y, bb.z, bb.w};
            #pragma unroll
            for (int i = 0; i < 4; i++)
                #pragma unroll
                for (int jj = 0; jj < 4; jj++)
                    sc[i][jj] += av[i] * bv_[jj];
        }
        #pragma unroll
        for (int i = 0; i < 4; i++) {
            const int gr = q0 + r0 + i;
            float rm = -1e30f;
            #pragma unroll
            for (int jj = 0; jj < 4; jj++) {
                float v = sc[i][jj] * RSC;
                if (k0 + c0 + jj > gr) v = -1e10f;   // causal mask (matches ref)
                sc[i][jj] = v;
                rm = fmaxf(rm, v);
            }
            #pragma unroll
            for (int off = 1; off < 16; off <<= 1)
                rm = fmaxf(rm, __shfl_xor_sync(0xffffffffu, rm, off));
            float mo = m_s[r0 + i];
            float mn = fmaxf(mo, rm);
            float rs = 0.f;
            #pragma unroll
            for (int jj = 0; jj < 4; jj++) {
                float p = __expf(sc[i][jj] - mn);
                sc[i][jj] = p;
                rs += p;
            }
            #pragma unroll
            for (int off = 1; off < 16; off <<= 1)
                rs += __shfl_xor_sync(0xffffffffu, rs, off);
            *(float4*)&Ps[r0 + i][c0] =
                make_float4(sc[i][0], sc[i][1], sc[i][2], sc[i][3]);
            if (tc == 0) {
                float al = __expf(mo - mn);
                m_s[r0 + i]  = mn;
                al_s[r0 + i] = al;
                l_s[r0 + i]  = l_s[r0 + i] * al + rs;
            }
        }
        __syncthreads();

        // ---- phase B: O += P @ V  (rescale by alpha first)
        float alpha = al_s[rb];
        #pragma unroll
        for (int c = 0; c < 32; c++) acc[c] *= alpha;
        for (int kk = 0; kk < 64; ++kk) {
            float p = Ps[rb][kk];
            #pragma unroll
            for (int u = 0; u < 8; u++) {
                float4 vv = *(float4*)&Vs[kk][cg * 4 + u * 16];
                acc[u * 4 + 0] += p * vv.x;
                acc[u * 4 + 1] += p * vv.y;
                acc[u * 4 + 2] += p * vv.z;
                acc[u * 4 + 3] += p * vv.w;
            }
        }
        __syncthreads();
    }

    const float linv = 1.f / l_s[rb];
    float* op = out + ((size_t)b * SEQ + q0 + rb) * HD;
    #pragma unroll
    for (int u = 0; u < 8; u++) {
        float4 o = make_float4(acc[u * 4 + 0] * linv, acc[u * 4 + 1] * linv,
                               acc[u * 4 + 2] * linv, acc[u * 4 + 3] * linv);
        *(float4*)(op + cg * 4 + u * 16) = o;
    }
}

// ---------------------------------------------------------------------------
extern "C" void kernel_launch(void* const* d_in, const int* in_sizes, int n_in,
                              void* d_out, int out_size)
{
    const float* X  = (const float*)d_in[0];
    const float* Wq = (const float*)d_in[1];
    const float* bq = (const float*)d_in[2];
    const float* Wk = (const float*)d_in[3];
    const float* bk = (const float*)d_in[4];
    const float* Wv = (const float*)d_in[5];
    const float* bv = (const float*)d_in[6];
    float* out = (float*)d_out;

    dim3 g1(128, 3);
    qkv_kernel<<<g1, 256>>>(X, Wq, bq, Wk, bk, Wv, bv);

    const int smem_bytes = ATTN_SMEM_FLOATS * (int)sizeof(float);
    cudaFuncSetAttribute(attn_kernel,
                         cudaFuncAttributeMaxDynamicSharedMemorySize, smem_bytes);
    dim3 g2(32, 4);
    attn_kernel<<<g2, 256, smem_bytes>>>(out);
}

// round 3
// speedup vs baseline: 1.5315x; 1.5315x over previous
#include <cuda_runtime.h>
#include <cuda_bf16.h>
#include <cstdint>

#define EMBED 2048
#define HD    128
#define NB    4
#define SEQ   2048

// ---------------------------------------------------------------------------
// Scratch globals
// ---------------------------------------------------------------------------
__device__ float g_qT[NB * HD * SEQ];                 // [b][d][s]
__device__ float g_kT[NB * HD * SEQ];                 // [b][d][s]
__device__ float g_v [NB * SEQ * HD];                 // [b][s][d]
__device__ __nv_bfloat16 g_Whi[3 * HD * EMBED];       // [wsel][n][k]  (K-major)
__device__ __nv_bfloat16 g_Wlo[3 * HD * EMBED];

__device__ __forceinline__ uint32_t pk2(__nv_bfloat16 a, __nv_bfloat16 b) {
    return ((uint32_t)__bfloat16_as_ushort(b) << 16) | __bfloat16_as_ushort(a);
}

// m16n8k16 row.col bf16 -> fp32 (sm_80+ PTX; valid on base sm_103 target)
__device__ __forceinline__ void mma16816(float* c, const uint32_t* a,
                                         const uint32_t* b) {
    asm volatile(
        "mma.sync.aligned.m16n8k16.row.col.f32.bf16.bf16.f32 "
        "{%0,%1,%2,%3}, {%4,%5,%6,%7}, {%8,%9}, {%0,%1,%2,%3};"
        : "+f"(c[0]), "+f"(c[1]), "+f"(c[2]), "+f"(c[3])
        : "r"(a[0]), "r"(a[1]), "r"(a[2]), "r"(a[3]), "r"(b[0]), "r"(b[1]));
}

// ---------------------------------------------------------------------------
// Prep: Wq|Wk|Wv fp32 [2048,128] -> K-major bf16 hi/lo [wsel][n][k]
// grid = (16, 3), 256 threads
// ---------------------------------------------------------------------------
__global__ __launch_bounds__(256)
void prep_w(const float* __restrict__ Wq, const float* __restrict__ Wk,
            const float* __restrict__ Wv)
{
    __shared__ float Ws[128][132];
    const int w  = blockIdx.y;
    const float* __restrict__ W = (w == 0) ? Wq : (w == 1 ? Wk : Wv);
    const int k0 = blockIdx.x * 128;
    const int t  = threadIdx.x;

    for (int l = 0; l < 64; ++l) {
        int idx = t + l * 256;
        int kk = idx >> 7, n = idx & 127;
        Ws[kk][n] = W[(size_t)(k0 + kk) * HD + n];
    }
    __syncthreads();

    const int n = t >> 1, kh = (t & 1) * 64;
    size_t base = (size_t)w * HD * EMBED + (size_t)n * EMBED + k0 + kh;
    #pragma unroll
    for (int g = 0; g < 8; ++g) {
        uint32_t hp[4], lp[4];
        #pragma unroll
        for (int q = 0; q < 4; ++q) {
            float x0 = Ws[kh + g * 8 + q * 2][n];
            float x1 = Ws[kh + g * 8 + q * 2 + 1][n];
            __nv_bfloat16 h0 = __float2bfloat16(x0);
            __nv_bfloat16 h1 = __float2bfloat16(x1);
            __nv_bfloat16 l0 = __float2bfloat16(x0 - __bfloat162float(h0));
            __nv_bfloat16 l1 = __float2bfloat16(x1 - __bfloat162float(h1));
            hp[q] = pk2(h0, h1);
            lp[q] = pk2(l0, l1);
        }
        *(uint4*)(g_Whi + base + g * 8) = make_uint4(hp[0], hp[1], hp[2], hp[3]);
        *(uint4*)(g_Wlo + base + g * 8) = make_uint4(lp[0], lp[1], lp[2], lp[3]);
    }
}

// ---------------------------------------------------------------------------
// QKV via mma.sync bf16 split precision (Ahi*Bhi + Ahi*Blo + Alo*Bhi).
// grid = (64, 3): (M-tile of 128 rows, wsel). 256 threads, warp tile 64x32.
// K chunks of 32 (2 x k16 steps), register prefetch of next gmem chunk.
// smem rows padded to 40 bf16 (80B): fragment loads are bank-conflict-free.
// ---------------------------------------------------------------------------
#define KC 32
#define LDB 40
#define OFF_AHI 0
#define OFF_ALO (128 * LDB * 2)
#define OFF_BHI (2 * 128 * LDB * 2)
#define OFF_BLO (3 * 128 * LDB * 2)
#define OFF_CT  (4 * 128 * LDB * 2)            // 40960
#define OFF_BIAS (OFF_CT + 128 * 132 * 4)      // 108544
#define QSM_TOTAL (OFF_BIAS + 512)

__global__ __launch_bounds__(256)
void qkv_mma(const float* __restrict__ X,
             const float* __restrict__ bq, const float* __restrict__ bk,
             const float* __restrict__ bv)
{
    extern __shared__ char smem[];
    __nv_bfloat16* Ahi = (__nv_bfloat16*)(smem + OFF_AHI);
    __nv_bfloat16* Alo = (__nv_bfloat16*)(smem + OFF_ALO);
    __nv_bfloat16* Bhi = (__nv_bfloat16*)(smem + OFF_BHI);
    __nv_bfloat16* Blo = (__nv_bfloat16*)(smem + OFF_BLO);
    float (*Ct)[132]   = (float (*)[132])(smem + OFF_CT);
    float* biasS       = (float*)(smem + OFF_BIAS);

    const int wsel = blockIdx.y;
    const int m0   = blockIdx.x * 128;
    const int t    = threadIdx.x;
    const int wid  = t >> 5, lane = t & 31;
    const int g    = lane >> 2, tig = lane & 3;
    const int wm   = wid & 1, wn = wid >> 1;      // 2 x 4 warp grid

    if (t < 128) {
        const float* bias = (wsel == 0) ? bq : (wsel == 1 ? bk : bv);
        biasS[t] = bias[t];
    }

    const __nv_bfloat16* WH = g_Whi + (size_t)wsel * HD * EMBED;
    const __nv_bfloat16* WL = g_Wlo + (size_t)wsel * HD * EMBED;

    // per-thread staging: row = t>>1, k-half = (t&1)*16
    const int srow = t >> 1, skh = (t & 1) * 16;

    float c[4][4][4];
    #pragma unroll
    for (int i = 0; i < 4; ++i)
        #pragma unroll
        for (int j = 0; j < 4; ++j)
            #pragma unroll
            for (int q = 0; q < 4; ++q) c[i][j][q] = 0.f;

    float4 aR[4];
    uint4  bH[2], bL[2];
    {
        const float* src = X + (size_t)(m0 + srow) * EMBED + skh;
        #pragma unroll
        for (int q = 0; q < 4; ++q) aR[q] = *(const float4*)(src + q * 4);
        const __nv_bfloat16* bsrc = WH + (size_t)srow * EMBED + skh;
        const __nv_bfloat16* lsrc = WL + (size_t)srow * EMBED + skh;
        bH[0] = *(const uint4*)bsrc;  bH[1] = *(const uint4*)(bsrc + 8);
        bL[0] = *(const uint4*)lsrc;  bL[1] = *(const uint4*)(lsrc + 8);
    }

    for (int kt = 0; kt < EMBED / KC; ++kt) {
        // stage current chunk into smem
        {
            uint32_t hp[8], lp[8];
            #pragma unroll
            for (int q = 0; q < 4; ++q) {
                float4 v = aR[q];
                __nv_bfloat16 h0 = __float2bfloat16(v.x), h1 = __float2bfloat16(v.y);
                __nv_bfloat16 h2 = __float2bfloat16(v.z), h3 = __float2bfloat16(v.w);
                __nv_bfloat16 l0 = __float2bfloat16(v.x - __bfloat162float(h0));
                __nv_bfloat16 l1 = __float2bfloat16(v.y - __bfloat162float(h1));
                __nv_bfloat16 l2 = __float2bfloat16(v.z - __bfloat162float(h2));
                __nv_bfloat16 l3 = __float2bfloat16(v.w - __bfloat162float(h3));
                hp[2 * q] = pk2(h0, h1); hp[2 * q + 1] = pk2(h2, h3);
                lp[2 * q] = pk2(l0, l1); lp[2 * q + 1] = pk2(l2, l3);
            }
            __nv_bfloat16* ad = Ahi + srow * LDB + skh;
            *(uint4*)(ad)     = make_uint4(hp[0], hp[1], hp[2], hp[3]);
            *(uint4*)(ad + 8) = make_uint4(hp[4], hp[5], hp[6], hp[7]);
            __nv_bfloat16* al = Alo + srow * LDB + skh;
            *(uint4*)(al)     = make_uint4(lp[0], lp[1], lp[2], lp[3]);
            *(uint4*)(al + 8) = make_uint4(lp[4], lp[5], lp[6], lp[7]);
            __nv_bfloat16* bd = Bhi + srow * LDB + skh;
            *(uint4*)(bd) = bH[0];  *(uint4*)(bd + 8) = bH[1];
            __nv_bfloat16* bl = Blo + srow * LDB + skh;
            *(uint4*)(bl) = bL[0];  *(uint4*)(bl + 8) = bL[1];
        }
        __syncthreads();

        // prefetch next chunk
        if (kt + 1 < EMBED / KC) {
            const int kb = (kt + 1) * KC;
            const float* src = X + (size_t)(m0 + srow) * EMBED + kb + skh;
            #pragma unroll
            for (int q = 0; q < 4; ++q) aR[q] = *(const float4*)(src + q * 4);
            const __nv_bfloat16* bsrc = WH + (size_t)srow * EMBED + kb + skh;
            const __nv_bfloat16* lsrc = WL + (size_t)srow * EMBED + kb + skh;
            bH[0] = *(const uint4*)bsrc;  bH[1] = *(const uint4*)(bsrc + 8);
            bL[0] = *(const uint4*)lsrc;  bL[1] = *(const uint4*)(lsrc + 8);
        }

        // 2 x k16 MMA steps
        #pragma unroll
        for (int ks = 0; ks < 2; ++ks) {
            const int k0 = ks * 16;
            uint32_t afh[4][4], afl[4][4];
            #pragma unroll
            for (int mi = 0; mi < 4; ++mi) {
                const int r = wm * 64 + mi * 16 + g;
                const int kk = k0 + tig * 2;
                afh[mi][0] = *(uint32_t*)&Ahi[r * LDB + kk];
                afh[mi][1] = *(uint32_t*)&Ahi[(r + 8) * LDB + kk];
                afh[mi][2] = *(uint32_t*)&Ahi[r * LDB + kk + 8];
                afh[mi][3] = *(uint32_t*)&Ahi[(r + 8) * LDB + kk + 8];
                afl[mi][0] = *(uint32_t*)&Alo[r * LDB + kk];
                afl[mi][1] = *(uint32_t*)&Alo[(r + 8) * LDB + kk];
                afl[mi][2] = *(uint32_t*)&Alo[r * LDB + kk + 8];
                afl[mi][3] = *(uint32_t*)&Alo[(r + 8) * LDB + kk + 8];
            }
            uint32_t bfh[4][2], bfl[4][2];
            #pragma unroll
            for (int ni = 0; ni < 4; ++ni) {
                const int n = wn * 32 + ni * 8 + g;
                const int kk = k0 + tig * 2;
                bfh[ni][0] = *(uint32_t*)&Bhi[n * LDB + kk];
                bfh[ni][1] = *(uint32_t*)&Bhi[n * LDB + kk + 8];
                bfl[ni][0] = *(uint32_t*)&Blo[n * LDB + kk];
                bfl[ni][1] = *(uint32_t*)&Blo[n * LDB + kk + 8];
            }
            #pragma unroll
            for (int mi = 0; mi < 4; ++mi)
                #pragma unroll
                for (int ni = 0; ni < 4; ++ni) {
                    mma16816(c[mi][ni], afh[mi], bfh[ni]);
                    mma16816(c[mi][ni], afh[mi], bfl[ni]);
                    mma16816(c[mi][ni], afl[mi], bfh[ni]);
                }
        }
        __syncthreads();
    }

    // ---- epilogue: frags (+bias) -> Ct staging
    #pragma unroll
    for (int mi = 0; mi < 4; ++mi) {
        const int r = wm * 64 + mi * 16 + g;
        #pragma unroll
        for (int ni = 0; ni < 4; ++ni) {
            const int n = wn * 32 + ni * 8 + tig * 2;
            Ct[r][n]         = c[mi][ni][0] + biasS[n];
            Ct[r][n + 1]     = c[mi][ni][1] + biasS[n + 1];
            Ct[r + 8][n]     = c[mi][ni][2] + biasS[n];
            Ct[r + 8][n + 1] = c[mi][ni][3] + biasS[n + 1];
        }
    }
    __syncthreads();

    const int batch = m0 >> 11, s0 = m0 & 2047;
    if (wsel < 2) {
        // transposed coalesced writeout: [d][s]
        float* dst = (wsel == 0 ? g_qT : g_kT) + (size_t)batch * HD * SEQ;
        const int d = t >> 1, sh = (t & 1) * 64;
        float* dp = dst + (size_t)d * SEQ + s0 + sh;
        #pragma unroll
        for (int q = 0; q < 16; ++q) {
            float4 v = make_float4(Ct[sh + q * 4 + 0][d], Ct[sh + q * 4 + 1][d],
                                   Ct[sh + q * 4 + 2][d], Ct[sh + q * 4 + 3][d]);
            *(float4*)(dp + q * 4) = v;
        }
    } else {
        float* dst = g_v + (size_t)batch * SEQ * HD;
        const int r = t >> 1, dh = (t & 1) * 64;
        float* dp = dst + (size_t)(s0 + r) * HD + dh;
        #pragma unroll
        for (int q = 0; q < 16; ++q)
            *(float4*)(dp + q * 4) = *(float4*)&Ct[r][dh + q * 4];
    }
}

// ---------------------------------------------------------------------------
// Attention: causal flash, fp32 SIMT, balanced pairing.
// grid = (32, 4). CTA x handles q-tiles {x, 63-x} (32 rows each);
// k-tiles 128 wide; every CTA does exactly 17 k-iterations.
// ---------------------------------------------------------------------------
#define ASM_FLOATS (128*36 + 128*132 + 128*132 + 32*132 + 96)

__global__ __launch_bounds__(256)
void attn2(float* __restrict__ out)
{
    extern __shared__ float sm[];
    float (*Qs)[36]  = (float (*)[36])sm;
    float (*Ks)[132] = (float (*)[132])(sm + 128 * 36);
    float (*Vs)[132] = (float (*)[132])(sm + 128 * 36 + 128 * 132);
    float (*Ps)[132] = (float (*)[132])(sm + 128 * 36 + 2 * 128 * 132);
    float* m_s  = sm + 128 * 36 + 2 * 128 * 132 + 32 * 132;
    float* l_s  = m_s + 32;
    float* al_s = l_s + 32;

    const int b = blockIdx.y, t = threadIdx.x;
    const float* __restrict__ qT = g_qT + (size_t)b * HD * SEQ;
    const float* __restrict__ kT = g_kT + (size_t)b * HD * SEQ;
    const float* __restrict__ vP = g_v  + (size_t)b * SEQ * HD;

    const int tr = t >> 5, r0 = tr * 4;          // phase A: warp w -> rows 4w..4w+3
    const int c0 = (t & 31) * 4;                 // phase A: 32 col groups
    const int rb = t >> 3, cg = t & 7;           // phase B
    const float RSC = 0.08838834764831845f;

    for (int subt = 0; subt < 2; ++subt) {
        const int jt = subt ? (63 - blockIdx.x) : blockIdx.x;
        const int q0 = jt * 32;
        const int iters = (jt >> 2) + 1;

        #pragma unroll
        for (int l = 0; l < 4; ++l) {
            int idx = t + l * 256;
            int d = idx >> 3, sq = idx & 7;
            *(float4*)&Qs[d][sq * 4] = *(const float4*)(qT + (size_t)d * SEQ + q0 + sq * 4);
        }
        if (t < 32) { m_s[t] = -1e30f; l_s[t] = 0.f; }
        float acc[16];
        #pragma unroll
        for (int cidx = 0; cidx < 16; ++cidx) acc[cidx] = 0.f;
        __syncthreads();

        for (int it = 0; it < iters; ++it) {
            const int k0 = it * 128;
            #pragma unroll
            for (int l = 0; l < 16; ++l) {
                int idx = t + l * 256;
                int d = idx >> 5, sq = idx & 31;
                *(float4*)&Ks[d][sq * 4] = *(const float4*)(kT + (size_t)d * SEQ + k0 + sq * 4);
            }
            #pragma unroll
            for (int l = 0; l < 16; ++l) {
                int idx = t + l * 256;
                int s = idx >> 5, cq = idx & 31;
                *(float4*)&Vs[s][cq * 4] = *(const float4*)(vP + (size_t)(k0 + s) * HD + cq * 4);
            }
            __syncthreads();

            // phase A: S = Q K^T (32x128) + mask + online softmax
            float sc[4][4];
            #pragma unroll
            for (int i = 0; i < 4; ++i)
                #pragma unroll
                for (int j = 0; j < 4; ++j) sc[i][j] = 0.f;
            for (int k = 0; k < 128; ++k) {
                float4 a  = *(float4*)&Qs[k][r0];
                float4 bb = *(float4*)&Ks[k][c0];
                float av[4]  = {a.x, a.y, a.z, a.w};
                float bv_[4] = {bb.x, bb.y, bb.z, bb.w};
                #pragma unroll
                for (int i = 0; i < 4; ++i)
                    #pragma unroll
                    for (int j = 0; j < 4; ++j)
                        sc[i][j] += av[i] * bv_[j];
            }
            #pragma unroll
            for (int i = 0; i < 4; ++i) {
                const int gr = q0 + r0 + i;
                float rm = -1e30f;
                #pragma unroll
                for (int j = 0; j < 4; ++j) {
                    float v = sc[i][j] * RSC;
                    if (k0 + c0 + j > gr) v = -1e10f;
                    sc[i][j] = v;
                    rm = fmaxf(rm, v);
                }
                #pragma unroll
                for (int off = 16; off >= 1; off >>= 1)
                    rm = fmaxf(rm, __shfl_xor_sync(0xffffffffu, rm, off));
                float mo = m_s[r0 + i];
                float mn = fmaxf(mo, rm);
                float rs = 0.f;
                #pragma unroll
                for (int j = 0; j < 4; ++j) {
                    float p = __expf(sc[i][j] - mn);
                    sc[i][j] = p;
                    rs += p;
                }
                #pragma unroll
                for (int off = 16; off >= 1; off >>= 1)
                    rs += __shfl_xor_sync(0xffffffffu, rs, off);
                *(float4*)&Ps[r0 + i][c0] =
                    make_float4(sc[i][0], sc[i][1], sc[i][2], sc[i][3]);
                if ((t & 31) == 0) {
                    float al = __expf(mo - mn);
                    m_s[r0 + i]  = mn;
                    al_s[r0 + i] = al;
                    l_s[r0 + i]  = l_s[r0 + i] * al + rs;
                }
            }
            __syncthreads();

            // phase B: O = alpha*O + P @ V
            const float alpha = al_s[rb];
            #pragma unroll
            for (int cidx = 0; cidx < 16; ++cidx) acc[cidx] *= alpha;
            for (int kk = 0; kk < 128; ++kk) {
                const float p = Ps[rb][kk];
                #pragma unroll
                for (int u = 0; u < 4; ++u) {
                    float4 vv = *(float4*)&Vs[kk][cg * 4 + u * 32];
                    acc[u * 4 + 0] += p * vv.x;
                    acc[u * 4 + 1] += p * vv.y;
                    acc[u * 4 + 2] += p * vv.z;
                    acc[u * 4 + 3] += p * vv.w;
                }
            }
            __syncthreads();
        }

        const float linv = 1.f / l_s[rb];
        float* op = out + ((size_t)b * SEQ + q0 + rb) * HD;
        #pragma unroll
        for (int u = 0; u < 4; ++u) {
            float4 o = make_float4(acc[u * 4 + 0] * linv, acc[u * 4 + 1] * linv,
                                   acc[u * 4 + 2] * linv, acc[u * 4 + 3] * linv);
            *(float4*)(op + cg * 4 + u * 32) = o;
        }
        __syncthreads();
    }
}

// ---------------------------------------------------------------------------
extern "C" void kernel_launch(void* const* d_in, const int* in_sizes, int n_in,
                              void* d_out, int out_size)
{
    const float* X  = (const float*)d_in[0];
    const float* Wq = (const float*)d_in[1];
    const float* bq = (const float*)d_in[2];
    const float* Wk = (const float*)d_in[3];
    const float* bk = (const float*)d_in[4];
    const float* Wv = (const float*)d_in[5];
    const float* bv = (const float*)d_in[6];
    float* out = (float*)d_out;

    prep_w<<<dim3(16, 3), 256>>>(Wq, Wk, Wv);

    cudaFuncSetAttribute(qkv_mma, cudaFuncAttributeMaxDynamicSharedMemorySize,
                         QSM_TOTAL);
    qkv_mma<<<dim3(64, 3), 256, QSM_TOTAL>>>(X, bq, bk, bv);

    const int asmb = ASM_FLOATS * (int)sizeof(float);
    cudaFuncSetAttribute(attn2, cudaFuncAttributeMaxDynamicSharedMemorySize, asmb);
    attn2<<<dim3(32, 4), 256, asmb>>>(out);
}

// round 5
// speedup vs baseline: 2.1984x; 1.4355x over previous
#include <cuda_runtime.h>
#include <cuda_bf16.h>
#include <cstdint>

#define EMBED 2048
#define HD    128
#define NB    4
#define SEQ   2048

// ---------------------------------------------------------------------------
// Scratch globals (bf16 hi/lo split operands)
// ---------------------------------------------------------------------------
__device__ __nv_bfloat16 g_Whi[3 * HD * EMBED];   // [wsel][n][k] K-major
__device__ __nv_bfloat16 g_Wlo[3 * HD * EMBED];
__device__ __nv_bfloat16 g_qhi[NB * SEQ * HD];    // [b][s][d]
__device__ __nv_bfloat16 g_qlo[NB * SEQ * HD];
__device__ __nv_bfloat16 g_khi[NB * SEQ * HD];    // [b][s][d]
__device__ __nv_bfloat16 g_klo[NB * SEQ * HD];
__device__ __nv_bfloat16 g_vthi[NB * HD * SEQ];   // [b][d][s]  (transposed)
__device__ __nv_bfloat16 g_vtlo[NB * HD * SEQ];

__device__ __forceinline__ uint32_t pk2(__nv_bfloat16 a, __nv_bfloat16 b) {
    return ((uint32_t)__bfloat16_as_ushort(b) << 16) | __bfloat16_as_ushort(a);
}
__device__ __forceinline__ uint32_t smem_u32(const void* p) {
    uint32_t a;
    asm("{ .reg .u64 t; cvta.to.shared.u64 t, %1; cvt.u32.u64 %0, t; }"
        : "=r"(a) : "l"(p));
    return a;
}
// m16n8k16 row.col bf16 -> fp32
__device__ __forceinline__ void mma16816(float* c, const uint32_t* a,
                                         const uint32_t* b) {
    asm volatile(
        "mma.sync.aligned.m16n8k16.row.col.f32.bf16.bf16.f32 "
        "{%0,%1,%2,%3}, {%4,%5,%6,%7}, {%8,%9}, {%0,%1,%2,%3};"
        : "+f"(c[0]), "+f"(c[1]), "+f"(c[2]), "+f"(c[3])
        : "r"(a[0]), "r"(a[1]), "r"(a[2]), "r"(a[3]), "r"(b[0]), "r"(b[1]));
}
__device__ __forceinline__ void ldsm4(uint32_t* r, uint32_t saddr) {
    asm volatile("ldmatrix.sync.aligned.m8n8.x4.shared.b16 {%0,%1,%2,%3}, [%4];"
                 : "=r"(r[0]), "=r"(r[1]), "=r"(r[2]), "=r"(r[3]) : "r"(saddr));
}

// ---------------------------------------------------------------------------
// Prep: Wq|Wk|Wv fp32 [2048,128] -> K-major bf16 hi/lo [wsel][n][k]
// ---------------------------------------------------------------------------
__global__ __launch_bounds__(256)
void prep_w(const float* __restrict__ Wq, const float* __restrict__ Wk,
            const float* __restrict__ Wv)
{
    __shared__ float Ws[128][132];
    const int w  = blockIdx.y;
    const float* __restrict__ W = (w == 0) ? Wq : (w == 1 ? Wk : Wv);
    const int k0 = blockIdx.x * 128;
    const int t  = threadIdx.x;

    for (int l = 0; l < 64; ++l) {
        int idx = t + l * 256;
        int kk = idx >> 7, n = idx & 127;
        Ws[kk][n] = W[(size_t)(k0 + kk) * HD + n];
    }
    __syncthreads();

    const int n = t >> 1, kh = (t & 1) * 64;
    size_t base = (size_t)w * HD * EMBED + (size_t)n * EMBED + k0 + kh;
    #pragma unroll
    for (int g = 0; g < 8; ++g) {
        uint32_t hp[4], lp[4];
        #pragma unroll
        for (int q = 0; q < 4; ++q) {
            float x0 = Ws[kh + g * 8 + q * 2][n];
            float x1 = Ws[kh + g * 8 + q * 2 + 1][n];
            __nv_bfloat16 h0 = __float2bfloat16(x0);
            __nv_bfloat16 h1 = __float2bfloat16(x1);
            __nv_bfloat16 l0 = __float2bfloat16(x0 - __bfloat162float(h0));
            __nv_bfloat16 l1 = __float2bfloat16(x1 - __bfloat162float(h1));
            hp[q] = pk2(h0, h1);
            lp[q] = pk2(l0, l1);
        }
        *(uint4*)(g_Whi + base + g * 8) = make_uint4(hp[0], hp[1], hp[2], hp[3]);
        *(uint4*)(g_Wlo + base + g * 8) = make_uint4(lp[0], lp[1], lp[2], lp[3]);
    }
}

// ---------------------------------------------------------------------------
// QKV via mma.sync bf16 split precision, ldmatrix fragments.
// grid = (64, 3). 256 threads, warp tile 64x32.
// ---------------------------------------------------------------------------
#define KC 32
#define LDB 40
#define OFF_AHI 0
#define OFF_ALO (128 * LDB * 2)
#define OFF_BHI (2 * 128 * LDB * 2)
#define OFF_BLO (3 * 128 * LDB * 2)
#define OFF_CT  (4 * 128 * LDB * 2)
#define OFF_BIAS (OFF_CT + 128 * 132 * 4)
#define QSM_TOTAL (OFF_BIAS + 512)

__global__ __launch_bounds__(256)
void qkv_mma(const float* __restrict__ X,
             const float* __restrict__ bq, const float* __restrict__ bk,
             const float* __restrict__ bv)
{
    extern __shared__ char smem[];
    __nv_bfloat16* Ahi = (__nv_bfloat16*)(smem + OFF_AHI);
    __nv_bfloat16* Alo = (__nv_bfloat16*)(smem + OFF_ALO);
    __nv_bfloat16* Bhi = (__nv_bfloat16*)(smem + OFF_BHI);
    __nv_bfloat16* Blo = (__nv_bfloat16*)(smem + OFF_BLO);
    float (*Ct)[132]   = (float (*)[132])(smem + OFF_CT);
    float* biasS       = (float*)(smem + OFF_BIAS);

    const int wsel = blockIdx.y;
    const int m0   = blockIdx.x * 128;
    const int t    = threadIdx.x;
    const int wid  = t >> 5, lane = t & 31;
    const int g    = lane >> 2, tig = lane & 3;
    const int wm   = wid & 1, wn = wid >> 1;

    const uint32_t sAhi = smem_u32(Ahi), sAlo = smem_u32(Alo);
    const uint32_t sBhi = smem_u32(Bhi), sBlo = smem_u32(Blo);
    const int ai_off = (((lane >> 3) & 1) * 8 + (lane & 7)) * LDB + (lane >> 4) * 8;
    const int bi_off = ((lane >> 4) * 8 + (lane & 7)) * LDB + ((lane >> 3) & 1) * 8;

    if (t < 128) {
        const float* bias = (wsel == 0) ? bq : (wsel == 1 ? bk : bv);
        biasS[t] = bias[t];
    }

    const __nv_bfloat16* WH = g_Whi + (size_t)wsel * HD * EMBED;
    const __nv_bfloat16* WL = g_Wlo + (size_t)wsel * HD * EMBED;
    const int srow = t >> 1, skh = (t & 1) * 16;

    float c[4][4][4];
    #pragma unroll
    for (int i = 0; i < 4; ++i)
        #pragma unroll
        for (int j = 0; j < 4; ++j)
            #pragma unroll
            for (int q = 0; q < 4; ++q) c[i][j][q] = 0.f;

    float4 aR[4];
    uint4  bH[2], bL[2];
    {
        const float* src = X + (size_t)(m0 + srow) * EMBED + skh;
        #pragma unroll
        for (int q = 0; q < 4; ++q) aR[q] = *(const float4*)(src + q * 4);
        const __nv_bfloat16* bsrc = WH + (size_t)srow * EMBED + skh;
        const __nv_bfloat16* lsrc = WL + (size_t)srow * EMBED + skh;
        bH[0] = *(const uint4*)bsrc;  bH[1] = *(const uint4*)(bsrc + 8);
        bL[0] = *(const uint4*)lsrc;  bL[1] = *(const uint4*)(lsrc + 8);
    }

    for (int kt = 0; kt < EMBED / KC; ++kt) {
        {
            uint32_t hp[8], lp[8];
            #pragma unroll
            for (int q = 0; q < 4; ++q) {
                float4 v = aR[q];
                __nv_bfloat16 h0 = __float2bfloat16(v.x), h1 = __float2bfloat16(v.y);
                __nv_bfloat16 h2 = __float2bfloat16(v.z), h3 = __float2bfloat16(v.w);
                __nv_bfloat16 l0 = __float2bfloat16(v.x - __bfloat162float(h0));
                __nv_bfloat16 l1 = __float2bfloat16(v.y - __bfloat162float(h1));
                __nv_bfloat16 l2 = __float2bfloat16(v.z - __bfloat162float(h2));
                __nv_bfloat16 l3 = __float2bfloat16(v.w - __bfloat162float(h3));
                hp[2 * q] = pk2(h0, h1); hp[2 * q + 1] = pk2(h2, h3);
                lp[2 * q] = pk2(l0, l1); lp[2 * q + 1] = pk2(l2, l3);
            }
            __nv_bfloat16* ad = Ahi + srow * LDB + skh;
            *(uint4*)(ad)     = make_uint4(hp[0], hp[1], hp[2], hp[3]);
            *(uint4*)(ad + 8) = make_uint4(hp[4], hp[5], hp[6], hp[7]);
            __nv_bfloat16* al = Alo + srow * LDB + skh;
            *(uint4*)(al)     = make_uint4(lp[0], lp[1], lp[2], lp[3]);
            *(uint4*)(al + 8) = make_uint4(lp[4], lp[5], lp[6], lp[7]);
            __nv_bfloat16* bd = Bhi + srow * LDB + skh;
            *(uint4*)(bd) = bH[0];  *(uint4*)(bd + 8) = bH[1];
            __nv_bfloat16* bl = Blo + srow * LDB + skh;
            *(uint4*)(bl) = bL[0];  *(uint4*)(bl + 8) = bL[1];
        }
        __syncthreads();

        if (kt + 1 < EMBED / KC) {
            const int kb = (kt + 1) * KC;
            const float* src = X + (size_t)(m0 + srow) * EMBED + kb + skh;
            #pragma unroll
            for (int q = 0; q < 4; ++q) aR[q] = *(const float4*)(src + q * 4);
            const __nv_bfloat16* bsrc = WH + (size_t)srow * EMBED + kb + skh;
            const __nv_bfloat16* lsrc = WL + (size_t)srow * EMBED + kb + skh;
            bH[0] = *(const uint4*)bsrc;  bH[1] = *(const uint4*)(bsrc + 8);
            bL[0] = *(const uint4*)lsrc;  bL[1] = *(const uint4*)(lsrc + 8);
        }

        #pragma unroll
        for (int ks = 0; ks < 2; ++ks) {
            const int k0s = ks * 16;
            uint32_t afh[4][4], afl[4][4], bh[2][4], bl[2][4];
            #pragma unroll
            for (int mi = 0; mi < 4; ++mi) {
                const uint32_t ro = 2 * ((wm * 64 + mi * 16) * LDB + k0s + ai_off);
                ldsm4(afh[mi], sAhi + ro);
                ldsm4(afl[mi], sAlo + ro);
            }
            #pragma unroll
            for (int h = 0; h < 2; ++h) {
                const uint32_t ro = 2 * ((wn * 32 + h * 16) * LDB + k0s + bi_off);
                ldsm4(bh[h], sBhi + ro);
                ldsm4(bl[h], sBlo + ro);
            }
            #pragma unroll
            for (int mi = 0; mi < 4; ++mi)
                #pragma unroll
                for (int nt = 0; nt < 4; ++nt) {
                    const uint32_t* bhp = &bh[nt >> 1][(nt & 1) * 2];
                    const uint32_t* blp = &bl[nt >> 1][(nt & 1) * 2];
                    mma16816(c[mi][nt], afh[mi], bhp);
                    mma16816(c[mi][nt], afh[mi], blp);
                    mma16816(c[mi][nt], afl[mi], bhp);
                }
        }
        __syncthreads();
    }

    // frags (+bias) -> Ct staging
    #pragma unroll
    for (int mi = 0; mi < 4; ++mi) {
        const int r = wm * 64 + mi * 16 + g;
        #pragma unroll
        for (int nt = 0; nt < 4; ++nt) {
            const int n = wn * 32 + nt * 8 + tig * 2;
            Ct[r][n]         = c[mi][nt][0] + biasS[n];
            Ct[r][n + 1]     = c[mi][nt][1] + biasS[n + 1];
            Ct[r + 8][n]     = c[mi][nt][2] + biasS[n];
            Ct[r + 8][n + 1] = c[mi][nt][3] + biasS[n + 1];
        }
    }
    __syncthreads();

    const int batch = m0 >> 11, s0 = m0 & 2047;
    if (wsel < 2) {
        const int r = t >> 1, dh = (t & 1) * 64;
        __nv_bfloat16* dhi = (wsel == 0 ? g_qhi : g_khi)
            + ((size_t)batch * SEQ + s0 + r) * HD + dh;
        __nv_bfloat16* dlo = (wsel == 0 ? g_qlo : g_klo)
            + ((size_t)batch * SEQ + s0 + r) * HD + dh;
        #pragma unroll
        for (int q = 0; q < 8; ++q) {
            uint32_t hp[4], lp[4];
            #pragma unroll
            for (int e = 0; e < 4; ++e) {
                float x0 = Ct[r][dh + q * 8 + e * 2];
                float x1 = Ct[r][dh + q * 8 + e * 2 + 1];
                __nv_bfloat16 h0 = __float2bfloat16(x0);
                __nv_bfloat16 h1 = __float2bfloat16(x1);
                hp[e] = pk2(h0, h1);
                lp[e] = pk2(__float2bfloat16(x0 - __bfloat162float(h0)),
                            __float2bfloat16(x1 - __bfloat162float(h1)));
            }
            *(uint4*)(dhi + q * 8) = make_uint4(hp[0], hp[1], hp[2], hp[3]);
            *(uint4*)(dlo + q * 8) = make_uint4(lp[0], lp[1], lp[2], lp[3]);
        }
    } else {
        const int d = t >> 1, sh = (t & 1) * 64;
        size_t base = ((size_t)batch * HD + d) * SEQ + s0 + sh;
        #pragma unroll
        for (int q = 0; q < 8; ++q) {
            uint32_t hp[4], lp[4];
            #pragma unroll
            for (int e = 0; e < 4; ++e) {
                float x0 = Ct[sh + q * 8 + e * 2][d];
                float x1 = Ct[sh + q * 8 + e * 2 + 1][d];
                __nv_bfloat16 h0 = __float2bfloat16(x0);
                __nv_bfloat16 h1 = __float2bfloat16(x1);
                hp[e] = pk2(h0, h1);
                lp[e] = pk2(__float2bfloat16(x0 - __bfloat162float(h0)),
                            __float2bfloat16(x1 - __bfloat162float(h1)));
            }
            *(uint4*)(g_vthi + base + q * 8) = make_uint4(hp[0], hp[1], hp[2], hp[3]);
            *(uint4*)(g_vtlo + base + q * 8) = make_uint4(lp[0], lp[1], lp[2], lp[3]);
        }
    }
}

// ---------------------------------------------------------------------------
// Attention v3b: mma.sync bf16, P split hi/lo (precision fix), balanced pairing.
// grid = (32, 4); CTA x does q-tiles {x, 63-x} (32 rows), k-tiles 128 wide.
// ---------------------------------------------------------------------------
#define LDK 136
#define LDPS 132
#define AOFF_QHI 0
#define AOFF_QLO (AOFF_QHI + 32 * LDK * 2)
#define AOFF_KHI (AOFF_QLO + 32 * LDK * 2)
#define AOFF_KLO (AOFF_KHI + 128 * LDK * 2)
#define AOFF_VHI (AOFF_KLO + 128 * LDK * 2)
#define AOFF_VLO (AOFF_VHI + 128 * LDK * 2)
#define AOFF_PS  (AOFF_VLO + 128 * LDK * 2)
#define AOFF_PB  (AOFF_PS  + 32 * LDPS * 4)
#define AOFF_PBL (AOFF_PB  + 32 * LDK * 2)
#define AOFF_MLA (AOFF_PBL + 32 * LDK * 2)
#define ASM_TOTAL (AOFF_MLA + 3 * 32 * 4)

__global__ __launch_bounds__(256)
void attn3(float* __restrict__ out)
{
    extern __shared__ char smem[];
    __nv_bfloat16* Qhi = (__nv_bfloat16*)(smem + AOFF_QHI);
    __nv_bfloat16* Qlo = (__nv_bfloat16*)(smem + AOFF_QLO);
    __nv_bfloat16* Khi = (__nv_bfloat16*)(smem + AOFF_KHI);
    __nv_bfloat16* Klo = (__nv_bfloat16*)(smem + AOFF_KLO);
    __nv_bfloat16* Vhi = (__nv_bfloat16*)(smem + AOFF_VHI);
    __nv_bfloat16* Vlo = (__nv_bfloat16*)(smem + AOFF_VLO);
    float*         Ps  = (float*)(smem + AOFF_PS);
    __nv_bfloat16* Pb  = (__nv_bfloat16*)(smem + AOFF_PB);
    __nv_bfloat16* Pbl = (__nv_bfloat16*)(smem + AOFF_PBL);
    float* m_s  = (float*)(smem + AOFF_MLA);
    float* l_s  = m_s + 32;
    float* al_s = l_s + 32;

    const int b = blockIdx.y, t = threadIdx.x;
    const int wid = t >> 5, lane = t & 31;
    const int g = lane >> 2, tig = lane & 3;
    const int wm = wid & 1, wn = wid >> 1;

    const uint32_t sQhi = smem_u32(Qhi), sQlo = smem_u32(Qlo);
    const uint32_t sKhi = smem_u32(Khi), sKlo = smem_u32(Klo);
    const uint32_t sVhi = smem_u32(Vhi), sVlo = smem_u32(Vlo);
    const uint32_t sPb  = smem_u32(Pb),  sPbl = smem_u32(Pbl);
    const int ai_off = (((lane >> 3) & 1) * 8 + (lane & 7)) * LDK + (lane >> 4) * 8;
    const int bi_off = ((lane >> 4) * 8 + (lane & 7)) * LDK + ((lane >> 3) & 1) * 8;

    const __nv_bfloat16* gQh = g_qhi + (size_t)b * SEQ * HD;
    const __nv_bfloat16* gQl = g_qlo + (size_t)b * SEQ * HD;
    const __nv_bfloat16* gKh = g_khi + (size_t)b * SEQ * HD;
    const __nv_bfloat16* gKl = g_klo + (size_t)b * SEQ * HD;
    const __nv_bfloat16* gVh = g_vthi + (size_t)b * HD * SEQ;
    const __nv_bfloat16* gVl = g_vtlo + (size_t)b * HD * SEQ;

    const float RSC = 0.08838834764831845f;  // 1/sqrt(128)
    const int sr = t >> 3, sc0 = (t & 7) * 16;

    for (int subt = 0; subt < 2; ++subt) {
        const int jt = subt ? (63 - blockIdx.x) : blockIdx.x;
        const int q0 = jt * 32;
        const int iters = (jt >> 2) + 1;

        {
            const int r = t >> 3, dq = (t & 7) * 16;
            const __nv_bfloat16* sh = gQh + (size_t)(q0 + r) * HD + dq;
            const __nv_bfloat16* sl = gQl + (size_t)(q0 + r) * HD + dq;
            *(uint4*)(Qhi + r * LDK + dq)     = *(const uint4*)sh;
            *(uint4*)(Qhi + r * LDK + dq + 8) = *(const uint4*)(sh + 8);
            *(uint4*)(Qlo + r * LDK + dq)     = *(const uint4*)sl;
            *(uint4*)(Qlo + r * LDK + dq + 8) = *(const uint4*)(sl + 8);
        }
        if (t < 32) { m_s[t] = -1e30f; l_s[t] = 0.f; }

        float o[4][4];
        #pragma unroll
        for (int nt = 0; nt < 4; ++nt)
            #pragma unroll
            for (int q = 0; q < 4; ++q) o[nt][q] = 0.f;

        for (int it = 0; it < iters; ++it) {
            const int k0 = it * 128;
            __syncthreads();
            {
                const int r = t >> 1, hh = (t & 1) * 64;
                const __nv_bfloat16* kh = gKh + (size_t)(k0 + r) * HD + hh;
                const __nv_bfloat16* kl = gKl + (size_t)(k0 + r) * HD + hh;
                const __nv_bfloat16* vh = gVh + (size_t)r * SEQ + k0 + hh;
                const __nv_bfloat16* vl = gVl + (size_t)r * SEQ + k0 + hh;
                __nv_bfloat16* dkh = Khi + r * LDK + hh;
                __nv_bfloat16* dkl = Klo + r * LDK + hh;
                __nv_bfloat16* dvh = Vhi + r * LDK + hh;
                __nv_bfloat16* dvl = Vlo + r * LDK + hh;
                #pragma unroll
                for (int q = 0; q < 8; ++q) {
                    *(uint4*)(dkh + q * 8) = *(const uint4*)(kh + q * 8);
                    *(uint4*)(dkl + q * 8) = *(const uint4*)(kl + q * 8);
                    *(uint4*)(dvh + q * 8) = *(const uint4*)(vh + q * 8);
                    *(uint4*)(dvl + q * 8) = *(const uint4*)(vl + q * 8);
                }
            }
            __syncthreads();

            // ---- QK^T (3-term split)
            float s4[4][4];
            #pragma unroll
            for (int nt = 0; nt < 4; ++nt)
                #pragma unroll
                for (int q = 0; q < 4; ++q) s4[nt][q] = 0.f;
            #pragma unroll
            for (int ks = 0; ks < 8; ++ks) {
                const int k0s = ks * 16;
                uint32_t qh[4], ql[4], kh[2][4], kl[2][4];
                const uint32_t ao = 2 * (wm * 16 * LDK + k0s + ai_off);
                ldsm4(qh, sQhi + ao);
                ldsm4(ql, sQlo + ao);
                #pragma unroll
                for (int h = 0; h < 2; ++h) {
                    const uint32_t bo = 2 * ((wn * 32 + h * 16) * LDK + k0s + bi_off);
                    ldsm4(kh[h], sKhi + bo);
                    ldsm4(kl[h], sKlo + bo);
                }
                #pragma unroll
                for (int nt = 0; nt < 4; ++nt) {
                    const uint32_t* bhp = &kh[nt >> 1][(nt & 1) * 2];
                    const uint32_t* blp = &kl[nt >> 1][(nt & 1) * 2];
                    mma16816(s4[nt], qh, bhp);
                    mma16816(s4[nt], qh, blp);
                    mma16816(s4[nt], ql, bhp);
                }
            }
            {
                const int row0 = wm * 16 + g;
                #pragma unroll
                for (int nt = 0; nt < 4; ++nt) {
                    const int col = wn * 32 + nt * 8 + tig * 2;
                    *(float2*)&Ps[row0 * LDPS + col] =
                        make_float2(s4[nt][0], s4[nt][1]);
                    *(float2*)&Ps[(row0 + 8) * LDPS + col] =
                        make_float2(s4[nt][2], s4[nt][3]);
                }
            }
            __syncthreads();

            // ---- softmax (fp32), pack P hi/lo bf16
            {
                const int gq = q0 + sr;
                float sv[16];
                float rm = -1e30f;
                #pragma unroll
                for (int j = 0; j < 16; ++j) {
                    float v = Ps[sr * LDPS + sc0 + j] * RSC;
                    if (k0 + sc0 + j > gq) v = -1e10f;
                    sv[j] = v;
                    rm = fmaxf(rm, v);
                }
                #pragma unroll
                for (int off = 4; off >= 1; off >>= 1)
                    rm = fmaxf(rm, __shfl_xor_sync(0xffffffffu, rm, off));
                const float mo = m_s[sr];
                const float mn = fmaxf(mo, rm);
                float rs = 0.f;
                uint32_t pph[8], ppl[8];
                #pragma unroll
                for (int j = 0; j < 8; ++j) {
                    float p0 = __expf(sv[2 * j] - mn);
                    float p1 = __expf(sv[2 * j + 1] - mn);
                    rs += p0 + p1;
                    __nv_bfloat16 h0 = __float2bfloat16(p0);
                    __nv_bfloat16 h1 = __float2bfloat16(p1);
                    pph[j] = pk2(h0, h1);
                    ppl[j] = pk2(__float2bfloat16(p0 - __bfloat162float(h0)),
                                 __float2bfloat16(p1 - __bfloat162float(h1)));
                }
                #pragma unroll
                for (int off = 4; off >= 1; off >>= 1)
                    rs += __shfl_xor_sync(0xffffffffu, rs, off);
                *(uint4*)(Pb  + sr * LDK + sc0)     = make_uint4(pph[0], pph[1], pph[2], pph[3]);
                *(uint4*)(Pb  + sr * LDK + sc0 + 8) = make_uint4(pph[4], pph[5], pph[6], pph[7]);
                *(uint4*)(Pbl + sr * LDK + sc0)     = make_uint4(ppl[0], ppl[1], ppl[2], ppl[3]);
                *(uint4*)(Pbl + sr * LDK + sc0 + 8) = make_uint4(ppl[4], ppl[5], ppl[6], ppl[7]);
                if ((t & 7) == 0) {
                    const float al = __expf(mo - mn);
                    m_s[sr]  = mn;
                    al_s[sr] = al;
                    l_s[sr]  = l_s[sr] * al + rs;
                }
            }
            __syncthreads();

            // ---- PV: O = alpha*O + Phi(Vhi+Vlo) + Plo*Vhi
            {
                const float a0 = al_s[wm * 16 + g];
                const float a1 = al_s[wm * 16 + g + 8];
                #pragma unroll
                for (int nt = 0; nt < 4; ++nt) {
                    o[nt][0] *= a0; o[nt][1] *= a0;
                    o[nt][2] *= a1; o[nt][3] *= a1;
                }
                #pragma unroll
                for (int ks = 0; ks < 8; ++ks) {
                    const int k0s = ks * 16;
                    uint32_t pa[4], pal[4], vh[2][4], vl[2][4];
                    const uint32_t po = 2 * (wm * 16 * LDK + k0s + ai_off);
                    ldsm4(pa,  sPb  + po);
                    ldsm4(pal, sPbl + po);
                    #pragma unroll
                    for (int h = 0; h < 2; ++h) {
                        const uint32_t bo = 2 * ((wn * 32 + h * 16) * LDK + k0s + bi_off);
                        ldsm4(vh[h], sVhi + bo);
                        ldsm4(vl[h], sVlo + bo);
                    }
                    #pragma unroll
                    for (int nt = 0; nt < 4; ++nt) {
                        const uint32_t* vhp = &vh[nt >> 1][(nt & 1) * 2];
                        const uint32_t* vlp = &vl[nt >> 1][(nt & 1) * 2];
                        mma16816(o[nt], pa,  vhp);
                        mma16816(o[nt], pa,  vlp);
                        mma16816(o[nt], pal, vhp);
                    }
                }
            }
        }

        // epilogue
        {
            const float li0 = 1.f / l_s[wm * 16 + g];
            const float li1 = 1.f / l_s[wm * 16 + g + 8];
            float* op0 = out + ((size_t)b * SEQ + q0 + wm * 16 + g) * HD;
            float* op1 = op0 + 8 * HD;
            #pragma unroll
            for (int nt = 0; nt < 4; ++nt) {
                const int d = wn * 32 + nt * 8 + tig * 2;
                *(float2*)(op0 + d) = make_float2(o[nt][0] * li0, o[nt][1] * li0);
                *(float2*)(op1 + d) = make_float2(o[nt][2] * li1, o[nt][3] * li1);
            }
        }
        __syncthreads();
    }
}

// ---------------------------------------------------------------------------
extern "C" void kernel_launch(void* const* d_in, const int* in_sizes, int n_in,
                              void* d_out, int out_size)
{
    const float* X  = (const float*)d_in[0];
    const float* Wq = (const float*)d_in[1];
    const float* bq = (const float*)d_in[2];
    const float* Wk = (const float*)d_in[3];
    const float* bk = (const float*)d_in[4];
    const float* Wv = (const float*)d_in[5];
    const float* bv = (const float*)d_in[6];
    float* out = (float*)d_out;

    prep_w<<<dim3(16, 3), 256>>>(Wq, Wk, Wv);

    cudaFuncSetAttribute(qkv_mma, cudaFuncAttributeMaxDynamicSharedMemorySize,
                         QSM_TOTAL);
    qkv_mma<<<dim3(64, 3), 256, QSM_TOTAL>>>(X, bq, bk, bv);

    cudaFuncSetAttribute(attn3, cudaFuncAttributeMaxDynamicSharedMemorySize,
                         ASM_TOTAL);
    attn3<<<dim3(32, 4), 256, ASM_TOTAL>>>(out);
}

// round 6
// speedup vs baseline: 2.4509x; 1.1148x over previous
#include <cuda_runtime.h>
#include <cuda_bf16.h>
#include <cstdint>

#define EMBED 2048
#define HD    128
#define NB    4
#define SEQ   2048

// ---------------------------------------------------------------------------
// Scratch globals (bf16 hi/lo split operands)
// ---------------------------------------------------------------------------
__device__ __align__(16) __nv_bfloat16 g_Whi[3 * HD * EMBED];   // [wsel][n][k]
__device__ __align__(16) __nv_bfloat16 g_Wlo[3 * HD * EMBED];
__device__ __align__(16) __nv_bfloat16 g_qhi[NB * SEQ * HD];    // [b][s][d]
__device__ __align__(16) __nv_bfloat16 g_qlo[NB * SEQ * HD];
__device__ __align__(16) __nv_bfloat16 g_khi[NB * SEQ * HD];    // [b][s][d]
__device__ __align__(16) __nv_bfloat16 g_klo[NB * SEQ * HD];
__device__ __align__(16) __nv_bfloat16 g_vthi[NB * HD * SEQ];   // [b][d][s]
__device__ __align__(16) __nv_bfloat16 g_vtlo[NB * HD * SEQ];

__device__ __forceinline__ uint32_t pk2(__nv_bfloat16 a, __nv_bfloat16 b) {
    return ((uint32_t)__bfloat16_as_ushort(b) << 16) | __bfloat16_as_ushort(a);
}
__device__ __forceinline__ uint32_t smem_u32(const void* p) {
    uint32_t a;
    asm("{ .reg .u64 t; cvta.to.shared.u64 t, %1; cvt.u32.u64 %0, t; }"
        : "=r"(a) : "l"(p));
    return a;
}
__device__ __forceinline__ void mma16816(float* c, const uint32_t* a,
                                         const uint32_t* b) {
    asm volatile(
        "mma.sync.aligned.m16n8k16.row.col.f32.bf16.bf16.f32 "
        "{%0,%1,%2,%3}, {%4,%5,%6,%7}, {%8,%9}, {%0,%1,%2,%3};"
        : "+f"(c[0]), "+f"(c[1]), "+f"(c[2]), "+f"(c[3])
        : "r"(a[0]), "r"(a[1]), "r"(a[2]), "r"(a[3]), "r"(b[0]), "r"(b[1]));
}
__device__ __forceinline__ void ldsm4(uint32_t* r, uint32_t saddr) {
    asm volatile("ldmatrix.sync.aligned.m8n8.x4.shared.b16 {%0,%1,%2,%3}, [%4];"
                 : "=r"(r[0]), "=r"(r[1]), "=r"(r[2]), "=r"(r[3]) : "r"(saddr));
}
__device__ __forceinline__ void cpa16(uint32_t dst, const void* src) {
    asm volatile("cp.async.cg.shared.global [%0], [%1], 16;"
                 :: "r"(dst), "l"(__cvta_generic_to_global(src)) : "memory");
}
#define CP_COMMIT() asm volatile("cp.async.commit_group;" ::: "memory")
#define CP_WAIT1()  asm volatile("cp.async.wait_group 1;" ::: "memory")

// ---------------------------------------------------------------------------
// Prep: Wq|Wk|Wv fp32 [2048,128] -> K-major bf16 hi/lo [wsel][n][k]
// ---------------------------------------------------------------------------
__global__ __launch_bounds__(256)
void prep_w(const float* __restrict__ Wq, const float* __restrict__ Wk,
            const float* __restrict__ Wv)
{
    __shared__ float Ws[128][132];
    const int w  = blockIdx.y;
    const float* __restrict__ W = (w == 0) ? Wq : (w == 1 ? Wk : Wv);
    const int k0 = blockIdx.x * 128;
    const int t  = threadIdx.x;

    for (int l = 0; l < 64; ++l) {
        int idx = t + l * 256;
        int kk = idx >> 7, n = idx & 127;
        Ws[kk][n] = W[(size_t)(k0 + kk) * HD + n];
    }
    __syncthreads();

    const int n = t >> 1, kh = (t & 1) * 64;
    size_t base = (size_t)w * HD * EMBED + (size_t)n * EMBED + k0 + kh;
    #pragma unroll
    for (int g = 0; g < 8; ++g) {
        uint32_t hp[4], lp[4];
        #pragma unroll
        for (int q = 0; q < 4; ++q) {
            float x0 = Ws[kh + g * 8 + q * 2][n];
            float x1 = Ws[kh + g * 8 + q * 2 + 1][n];
            __nv_bfloat16 h0 = __float2bfloat16(x0);
            __nv_bfloat16 h1 = __float2bfloat16(x1);
            __nv_bfloat16 l0 = __float2bfloat16(x0 - __bfloat162float(h0));
            __nv_bfloat16 l1 = __float2bfloat16(x1 - __bfloat162float(h1));
            hp[q] = pk2(h0, h1);
            lp[q] = pk2(l0, l1);
        }
        *(uint4*)(g_Whi + base + g * 8) = make_uint4(hp[0], hp[1], hp[2], hp[3]);
        *(uint4*)(g_Wlo + base + g * 8) = make_uint4(lp[0], lp[1], lp[2], lp[3]);
    }
}

// ---------------------------------------------------------------------------
// QKV via mma.sync bf16 split precision (unchanged from passing round-5 kernel)
// ---------------------------------------------------------------------------
#define KC 32
#define LDB 40
#define OFF_AHI 0
#define OFF_ALO (128 * LDB * 2)
#define OFF_BHI (2 * 128 * LDB * 2)
#define OFF_BLO (3 * 128 * LDB * 2)
#define OFF_CT  (4 * 128 * LDB * 2)
#define OFF_BIAS (OFF_CT + 128 * 132 * 4)
#define QSM_TOTAL (OFF_BIAS + 512)

__global__ __launch_bounds__(256)
void qkv_mma(const float* __restrict__ X,
             const float* __restrict__ bq, const float* __restrict__ bk,
             const float* __restrict__ bv)
{
    extern __shared__ char smem[];
    __nv_bfloat16* Ahi = (__nv_bfloat16*)(smem + OFF_AHI);
    __nv_bfloat16* Alo = (__nv_bfloat16*)(smem + OFF_ALO);
    __nv_bfloat16* Bhi = (__nv_bfloat16*)(smem + OFF_BHI);
    __nv_bfloat16* Blo = (__nv_bfloat16*)(smem + OFF_BLO);
    float (*Ct)[132]   = (float (*)[132])(smem + OFF_CT);
    float* biasS       = (float*)(smem + OFF_BIAS);

    const int wsel = blockIdx.y;
    const int m0   = blockIdx.x * 128;
    const int t    = threadIdx.x;
    const int wid  = t >> 5, lane = t & 31;
    const int g    = lane >> 2, tig = lane & 3;
    const int wm   = wid & 1, wn = wid >> 1;

    const uint32_t sAhi = smem_u32(Ahi), sAlo = smem_u32(Alo);
    const uint32_t sBhi = smem_u32(Bhi), sBlo = smem_u32(Blo);
    const int ai_off = (((lane >> 3) & 1) * 8 + (lane & 7)) * LDB + (lane >> 4) * 8;
    const int bi_off = ((lane >> 4) * 8 + (lane & 7)) * LDB + ((lane >> 3) & 1) * 8;

    if (t < 128) {
        const float* bias = (wsel == 0) ? bq : (wsel == 1 ? bk : bv);
        biasS[t] = bias[t];
    }

    const __nv_bfloat16* WH = g_Whi + (size_t)wsel * HD * EMBED;
    const __nv_bfloat16* WL = g_Wlo + (size_t)wsel * HD * EMBED;
    const int srow = t >> 1, skh = (t & 1) * 16;

    float c[4][4][4];
    #pragma unroll
    for (int i = 0; i < 4; ++i)
        #pragma unroll
        for (int j = 0; j < 4; ++j)
            #pragma unroll
            for (int q = 0; q < 4; ++q) c[i][j][q] = 0.f;

    float4 aR[4];
    uint4  bH[2], bL[2];
    {
        const float* src = X + (size_t)(m0 + srow) * EMBED + skh;
        #pragma unroll
        for (int q = 0; q < 4; ++q) aR[q] = *(const float4*)(src + q * 4);
        const __nv_bfloat16* bsrc = WH + (size_t)srow * EMBED + skh;
        const __nv_bfloat16* lsrc = WL + (size_t)srow * EMBED + skh;
        bH[0] = *(const uint4*)bsrc;  bH[1] = *(const uint4*)(bsrc + 8);
        bL[0] = *(const uint4*)lsrc;  bL[1] = *(const uint4*)(lsrc + 8);
    }

    for (int kt = 0; kt < EMBED / KC; ++kt) {
        {
            uint32_t hp[8], lp[8];
            #pragma unroll
            for (int q = 0; q < 4; ++q) {
                float4 v = aR[q];
                __nv_bfloat16 h0 = __float2bfloat16(v.x), h1 = __float2bfloat16(v.y);
                __nv_bfloat16 h2 = __float2bfloat16(v.z), h3 = __float2bfloat16(v.w);
                __nv_bfloat16 l0 = __float2bfloat16(v.x - __bfloat162float(h0));
                __nv_bfloat16 l1 = __float2bfloat16(v.y - __bfloat162float(h1));
                __nv_bfloat16 l2 = __float2bfloat16(v.z - __bfloat162float(h2));
                __nv_bfloat16 l3 = __float2bfloat16(v.w - __bfloat162float(h3));
                hp[2 * q] = pk2(h0, h1); hp[2 * q + 1] = pk2(h2, h3);
                lp[2 * q] = pk2(l0, l1); lp[2 * q + 1] = pk2(l2, l3);
            }
            __nv_bfloat16* ad = Ahi + srow * LDB + skh;
            *(uint4*)(ad)     = make_uint4(hp[0], hp[1], hp[2], hp[3]);
            *(uint4*)(ad + 8) = make_uint4(hp[4], hp[5], hp[6], hp[7]);
            __nv_bfloat16* al = Alo + srow * LDB + skh;
            *(uint4*)(al)     = make_uint4(lp[0], lp[1], lp[2], lp[3]);
            *(uint4*)(al + 8) = make_uint4(lp[4], lp[5], lp[6], lp[7]);
            __nv_bfloat16* bd = Bhi + srow * LDB + skh;
            *(uint4*)(bd) = bH[0];  *(uint4*)(bd + 8) = bH[1];
            __nv_bfloat16* bl = Blo + srow * LDB + skh;
            *(uint4*)(bl) = bL[0];  *(uint4*)(bl + 8) = bL[1];
        }
        __syncthreads();

        if (kt + 1 < EMBED / KC) {
            const int kb = (kt + 1) * KC;
            const float* src = X + (size_t)(m0 + srow) * EMBED + kb + skh;
            #pragma unroll
            for (int q = 0; q < 4; ++q) aR[q] = *(const float4*)(src + q * 4);
            const __nv_bfloat16* bsrc = WH + (size_t)srow * EMBED + kb + skh;
            const __nv_bfloat16* lsrc = WL + (size_t)srow * EMBED + kb + skh;
            bH[0] = *(const uint4*)bsrc;  bH[1] = *(const uint4*)(bsrc + 8);
            bL[0] = *(const uint4*)lsrc;  bL[1] = *(const uint4*)(lsrc + 8);
        }

        #pragma unroll
        for (int ks = 0; ks < 2; ++ks) {
            const int k0s = ks * 16;
            uint32_t afh[4][4], afl[4][4], bh[2][4], bl[2][4];
            #pragma unroll
            for (int mi = 0; mi < 4; ++mi) {
                const uint32_t ro = 2 * ((wm * 64 + mi * 16) * LDB + k0s + ai_off);
                ldsm4(afh[mi], sAhi + ro);
                ldsm4(afl[mi], sAlo + ro);
            }
            #pragma unroll
            for (int h = 0; h < 2; ++h) {
                const uint32_t ro = 2 * ((wn * 32 + h * 16) * LDB + k0s + bi_off);
                ldsm4(bh[h], sBhi + ro);
                ldsm4(bl[h], sBlo + ro);
            }
            #pragma unroll
            for (int mi = 0; mi < 4; ++mi)
                #pragma unroll
                for (int nt = 0; nt < 4; ++nt) {
                    const uint32_t* bhp = &bh[nt >> 1][(nt & 1) * 2];
                    const uint32_t* blp = &bl[nt >> 1][(nt & 1) * 2];
                    mma16816(c[mi][nt], afh[mi], bhp);
                    mma16816(c[mi][nt], afh[mi], blp);
                    mma16816(c[mi][nt], afl[mi], bhp);
                }
        }
        __syncthreads();
    }

    #pragma unroll
    for (int mi = 0; mi < 4; ++mi) {
        const int r = wm * 64 + mi * 16 + g;
        #pragma unroll
        for (int nt = 0; nt < 4; ++nt) {
            const int n = wn * 32 + nt * 8 + tig * 2;
            Ct[r][n]         = c[mi][nt][0] + biasS[n];
            Ct[r][n + 1]     = c[mi][nt][1] + biasS[n + 1];
            Ct[r + 8][n]     = c[mi][nt][2] + biasS[n];
            Ct[r + 8][n + 1] = c[mi][nt][3] + biasS[n + 1];
        }
    }
    __syncthreads();

    const int batch = m0 >> 11, s0 = m0 & 2047;
    if (wsel < 2) {
        const int r = t >> 1, dh = (t & 1) * 64;
        __nv_bfloat16* dhi = (wsel == 0 ? g_qhi : g_khi)
            + ((size_t)batch * SEQ + s0 + r) * HD + dh;
        __nv_bfloat16* dlo = (wsel == 0 ? g_qlo : g_klo)
            + ((size_t)batch * SEQ + s0 + r) * HD + dh;
        #pragma unroll
        for (int q = 0; q < 8; ++q) {
            uint32_t hp[4], lp[4];
            #pragma unroll
            for (int e = 0; e < 4; ++e) {
                float x0 = Ct[r][dh + q * 8 + e * 2];
                float x1 = Ct[r][dh + q * 8 + e * 2 + 1];
                __nv_bfloat16 h0 = __float2bfloat16(x0);
                __nv_bfloat16 h1 = __float2bfloat16(x1);
                hp[e] = pk2(h0, h1);
                lp[e] = pk2(__float2bfloat16(x0 - __bfloat162float(h0)),
                            __float2bfloat16(x1 - __bfloat162float(h1)));
            }
            *(uint4*)(dhi + q * 8) = make_uint4(hp[0], hp[1], hp[2], hp[3]);
            *(uint4*)(dlo + q * 8) = make_uint4(lp[0], lp[1], lp[2], lp[3]);
        }
    } else {
        const int d = t >> 1, sh = (t & 1) * 64;
        size_t base = ((size_t)batch * HD + d) * SEQ + s0 + sh;
        #pragma unroll
        for (int q = 0; q < 8; ++q) {
            uint32_t hp[4], lp[4];
            #pragma unroll
            for (int e = 0; e < 4; ++e) {
                float x0 = Ct[sh + q * 8 + e * 2][d];
                float x1 = Ct[sh + q * 8 + e * 2 + 1][d];
                __nv_bfloat16 h0 = __float2bfloat16(x0);
                __nv_bfloat16 h1 = __float2bfloat16(x1);
                hp[e] = pk2(h0, h1);
                lp[e] = pk2(__float2bfloat16(x0 - __bfloat162float(h0)),
                            __float2bfloat16(x1 - __bfloat162float(h1)));
            }
            *(uint4*)(g_vthi + base + q * 8) = make_uint4(hp[0], hp[1], hp[2], hp[3]);
            *(uint4*)(g_vtlo + base + q * 8) = make_uint4(lp[0], lp[1], lp[2], lp[3]);
        }
    }
}

// ---------------------------------------------------------------------------
// Attention v4: cp.async 2-stage pipelined K/V, 64-wide k-subtiles,
// mma.sync bf16 3-term splits, balanced causal pairing.
// grid = (32, 4); CTA x does q-tiles {x, 63-x} (32 rows); 33 iters each.
// ---------------------------------------------------------------------------
#define KT   64
#define LDK  136      // Q and K rows (d-width 128 + 8)
#define LDV  72       // V rows (k-width 64 + 8)
#define LDP  72       // P rows (k-width 64 + 8)
#define SPS  68       // Ps float stride

#define AO_QHI  0
#define AO_QLO  (AO_QHI + 32 * LDK * 2)                 // 8704
#define AO_KHI  (AO_QLO + 32 * LDK * 2)                 // 17408
#define AO_KLO  (AO_KHI + 2 * KT * LDK * 2)             // 52224
#define AO_VHI  (AO_KLO + 2 * KT * LDK * 2)             // 87040
#define AO_VLO  (AO_VHI + 2 * HD * LDV * 2)             // 123904
#define AO_PS   (AO_VLO + 2 * HD * LDV * 2)             // 160768
#define AO_PB   (AO_PS  + 32 * SPS * 4)                 // 169472
#define AO_PBL  (AO_PB  + 32 * LDP * 2)                 // 174080
#define AO_MLA  (AO_PBL + 32 * LDP * 2)                 // 178688
#define ASM_TOTAL (AO_MLA + 3 * 32 * 4)                 // 179072

__global__ __launch_bounds__(256)
void attn4(float* __restrict__ out)
{
    extern __shared__ char smem[];
    const uint32_t sb = smem_u32(smem);
    float* Ps   = (float*)(smem + AO_PS);
    float* m_s  = (float*)(smem + AO_MLA);
    float* l_s  = m_s + 32;
    float* al_s = l_s + 32;

    const int b = blockIdx.y, t = threadIdx.x;
    const int wid = t >> 5, lane = t & 31;
    const int g = lane >> 2, tig = lane & 3;
    const int wm = wid & 1, wn = wid >> 1;

    // fragment lane offsets (elements)
    const int aiQ = (((lane >> 3) & 1) * 8 + (lane & 7)) * LDK + (lane >> 4) * 8;
    const int biK = ((lane >> 4) * 8 + (lane & 7)) * LDK + ((lane >> 3) & 1) * 8;
    const int aiP = (((lane >> 3) & 1) * 8 + (lane & 7)) * LDP + (lane >> 4) * 8;
    const int biV = ((lane >> 4) * 8 + (lane & 7)) * LDV + ((lane >> 3) & 1) * 8;

    const __nv_bfloat16* gQh = g_qhi + (size_t)b * SEQ * HD;
    const __nv_bfloat16* gQl = g_qlo + (size_t)b * SEQ * HD;
    const __nv_bfloat16* gKh = g_khi + (size_t)b * SEQ * HD;
    const __nv_bfloat16* gKl = g_klo + (size_t)b * SEQ * HD;
    const __nv_bfloat16* gVh = g_vthi + (size_t)b * HD * SEQ;
    const __nv_bfloat16* gVl = g_vtlo + (size_t)b * HD * SEQ;

    const float RSC = 0.08838834764831845f;
    const int sr = t >> 3, sc0 = (t & 7) * 8;

    // cp.async per-thread mappings
    const int kr = t >> 2, kq = t & 3;          // K: row 0..63, quarter
    const int vr = t >> 1, vhh = t & 1;         // V: d-row 0..127, half

    for (int subt = 0; subt < 2; ++subt) {
        const int jt = subt ? (63 - blockIdx.x) : blockIdx.x;
        const int q0 = jt * 32;
        const int iters = (jt >> 1) + 1;

        // Q tile (plain loads; visible after first loop sync)
        {
            const int r = t >> 3, dq = (t & 7) * 16;
            const __nv_bfloat16* sh = gQh + (size_t)(q0 + r) * HD + dq;
            const __nv_bfloat16* sl = gQl + (size_t)(q0 + r) * HD + dq;
            *(uint4*)(smem + AO_QHI + (r * LDK + dq) * 2)      = *(const uint4*)sh;
            *(uint4*)(smem + AO_QHI + (r * LDK + dq + 8) * 2)  = *(const uint4*)(sh + 8);
            *(uint4*)(smem + AO_QLO + (r * LDK + dq) * 2)      = *(const uint4*)sl;
            *(uint4*)(smem + AO_QLO + (r * LDK + dq + 8) * 2)  = *(const uint4*)(sl + 8);
        }
        if (t < 32) { m_s[t] = -1e30f; l_s[t] = 0.f; }

        float o[4][4];
        #pragma unroll
        for (int nt = 0; nt < 4; ++nt)
            #pragma unroll
            for (int q = 0; q < 4; ++q) o[nt][q] = 0.f;

        // ---- pipeline prologue: issue tiles 0 and 1
        #pragma unroll
        for (int pi = 0; pi < 2; ++pi) {
            if (pi < iters) {
                const int k0 = pi * KT;
                const uint32_t kh_d = sb + AO_KHI + pi * (KT * LDK * 2) + kr * (LDK * 2) + kq * 64;
                const uint32_t kl_d = sb + AO_KLO + pi * (KT * LDK * 2) + kr * (LDK * 2) + kq * 64;
                const uint32_t vh_d = sb + AO_VHI + pi * (HD * LDV * 2) + vr * (LDV * 2) + vhh * 64;
                const uint32_t vl_d = sb + AO_VLO + pi * (HD * LDV * 2) + vr * (LDV * 2) + vhh * 64;
                const __nv_bfloat16* ksh = gKh + (size_t)(k0 + kr) * HD + kq * 32;
                const __nv_bfloat16* ksl = gKl + (size_t)(k0 + kr) * HD + kq * 32;
                const __nv_bfloat16* vsh = gVh + (size_t)vr * SEQ + k0 + vhh * 32;
                const __nv_bfloat16* vsl = gVl + (size_t)vr * SEQ + k0 + vhh * 32;
                #pragma unroll
                for (int j = 0; j < 4; ++j) {
                    cpa16(kh_d + j * 16, ksh + j * 8);
                    cpa16(kl_d + j * 16, ksl + j * 8);
                    cpa16(vh_d + j * 16, vsh + j * 8);
                    cpa16(vl_d + j * 16, vsl + j * 8);
                }
            }
            CP_COMMIT();
        }

        for (int it = 0; it < iters; ++it) {
            const int k0 = it * KT;
            const int st = it & 1;
            const uint32_t sKhi = sb + AO_KHI + st * (KT * LDK * 2);
            const uint32_t sKlo = sb + AO_KLO + st * (KT * LDK * 2);
            const uint32_t sVhi = sb + AO_VHI + st * (HD * LDV * 2);
            const uint32_t sVlo = sb + AO_VLO + st * (HD * LDV * 2);

            CP_WAIT1();
            __syncthreads();

            // ---- QK^T: S(32x64), 3-term split; warp = 16 rows x 16 cols
            float s4[2][4];
            #pragma unroll
            for (int nt = 0; nt < 2; ++nt)
                #pragma unroll
                for (int q = 0; q < 4; ++q) s4[nt][q] = 0.f;
            #pragma unroll
            for (int ks = 0; ks < 8; ++ks) {
                const int k0s = ks * 16;
                uint32_t qh[4], ql[4], kh[4], kl[4];
                const uint32_t ao = 2 * (wm * 16 * LDK + k0s + aiQ);
                ldsm4(qh, sb + AO_QHI + ao);
                ldsm4(ql, sb + AO_QLO + ao);
                const uint32_t bo = 2 * (wn * 16 * LDK + k0s + biK);
                ldsm4(kh, sKhi + bo);
                ldsm4(kl, sKlo + bo);
                #pragma unroll
                for (int nt = 0; nt < 2; ++nt) {
                    mma16816(s4[nt], qh, &kh[nt * 2]);
                    mma16816(s4[nt], qh, &kl[nt * 2]);
                    mma16816(s4[nt], ql, &kh[nt * 2]);
                }
            }
            {
                const int row0 = wm * 16 + g;
                #pragma unroll
                for (int nt = 0; nt < 2; ++nt) {
                    const int col = wn * 16 + nt * 8 + tig * 2;
                    *(float2*)&Ps[row0 * SPS + col] = make_float2(s4[nt][0], s4[nt][1]);
                    *(float2*)&Ps[(row0 + 8) * SPS + col] = make_float2(s4[nt][2], s4[nt][3]);
                }
            }
            __syncthreads();

            // ---- softmax: 8 threads/row, 8 cols each
            {
                const int gq = q0 + sr;
                float sv[8];
                float rm = -1e30f;
                #pragma unroll
                for (int j = 0; j < 8; ++j) {
                    float v = Ps[sr * SPS + sc0 + j] * RSC;
                    if (k0 + sc0 + j > gq) v = -1e10f;
                    sv[j] = v;
                    rm = fmaxf(rm, v);
                }
                #pragma unroll
                for (int off = 4; off >= 1; off >>= 1)
                    rm = fmaxf(rm, __shfl_xor_sync(0xffffffffu, rm, off));
                const float mo = m_s[sr];
                const float mn = fmaxf(mo, rm);
                float rs = 0.f;
                uint32_t pph[4], ppl[4];
                #pragma unroll
                for (int j = 0; j < 4; ++j) {
                    float p0 = __expf(sv[2 * j] - mn);
                    float p1 = __expf(sv[2 * j + 1] - mn);
                    rs += p0 + p1;
                    __nv_bfloat16 h0 = __float2bfloat16(p0);
                    __nv_bfloat16 h1 = __float2bfloat16(p1);
                    pph[j] = pk2(h0, h1);
                    ppl[j] = pk2(__float2bfloat16(p0 - __bfloat162float(h0)),
                                 __float2bfloat16(p1 - __bfloat162float(h1)));
                }
                #pragma unroll
                for (int off = 4; off >= 1; off >>= 1)
                    rs += __shfl_xor_sync(0xffffffffu, rs, off);
                *(uint4*)(smem + AO_PB  + (sr * LDP + sc0) * 2) =
                    make_uint4(pph[0], pph[1], pph[2], pph[3]);
                *(uint4*)(smem + AO_PBL + (sr * LDP + sc0) * 2) =
                    make_uint4(ppl[0], ppl[1], ppl[2], ppl[3]);
                if ((t & 7) == 0) {
                    const float al = __expf(mo - mn);
                    m_s[sr]  = mn;
                    al_s[sr] = al;
                    l_s[sr]  = l_s[sr] * al + rs;
                }
            }
            __syncthreads();

            // ---- PV: O = alpha*O + Phi(Vhi+Vlo) + Plo*Vhi ; warp = 16 rows x 32 d
            {
                const float a0 = al_s[wm * 16 + g];
                const float a1 = al_s[wm * 16 + g + 8];
                #pragma unroll
                for (int nt = 0; nt < 4; ++nt) {
                    o[nt][0] *= a0; o[nt][1] *= a0;
                    o[nt][2] *= a1; o[nt][3] *= a1;
                }
                #pragma unroll
                for (int ks = 0; ks < 4; ++ks) {
                    const int k0s = ks * 16;
                    uint32_t pa[4], pal[4], vh[2][4], vl[2][4];
                    const uint32_t po = 2 * (wm * 16 * LDP + k0s + aiP);
                    ldsm4(pa,  sb + AO_PB  + po);
                    ldsm4(pal, sb + AO_PBL + po);
                    #pragma unroll
                    for (int h = 0; h < 2; ++h) {
                        const uint32_t bo = 2 * ((wn * 32 + h * 16) * LDV + k0s + biV);
                        ldsm4(vh[h], sVhi + bo);
                        ldsm4(vl[h], sVlo + bo);
                    }
                    #pragma unroll
                    for (int nt = 0; nt < 4; ++nt) {
                        const uint32_t* vhp = &vh[nt >> 1][(nt & 1) * 2];
                        const uint32_t* vlp = &vl[nt >> 1][(nt & 1) * 2];
                        mma16816(o[nt], pa,  vhp);
                        mma16816(o[nt], pa,  vlp);
                        mma16816(o[nt], pal, vhp);
                    }
                }
            }
            __syncthreads();   // stage st consumed; Pb/Ps free

            // ---- prefetch tile it+2 into stage st
            if (it + 2 < iters) {
                const int kn = (it + 2) * KT;
                const uint32_t kh_d = sb + AO_KHI + st * (KT * LDK * 2) + kr * (LDK * 2) + kq * 64;
                const uint32_t kl_d = sb + AO_KLO + st * (KT * LDK * 2) + kr * (LDK * 2) + kq * 64;
                const uint32_t vh_d = sb + AO_VHI + st * (HD * LDV * 2) + vr * (LDV * 2) + vhh * 64;
                const uint32_t vl_d = sb + AO_VLO + st * (HD * LDV * 2) + vr * (LDV * 2) + vhh * 64;
                const __nv_bfloat16* ksh = gKh + (size_t)(kn + kr) * HD + kq * 32;
                const __nv_bfloat16* ksl = gKl + (size_t)(kn + kr) * HD + kq * 32;
                const __nv_bfloat16* vsh = gVh + (size_t)vr * SEQ + kn + vhh * 32;
                const __nv_bfloat16* vsl = gVl + (size_t)vr * SEQ + kn + vhh * 32;
                #pragma unroll
                for (int j = 0; j < 4; ++j) {
                    cpa16(kh_d + j * 16, ksh + j * 8);
                    cpa16(kl_d + j * 16, ksl + j * 8);
                    cpa16(vh_d + j * 16, vsh + j * 8);
                    cpa16(vl_d + j * 16, vsl + j * 8);
                }
            }
            CP_COMMIT();
        }

        // ---- epilogue
        {
            const float li0 = 1.f / l_s[wm * 16 + g];
            const float li1 = 1.f / l_s[wm * 16 + g + 8];
            float* op0 = out + ((size_t)b * SEQ + q0 + wm * 16 + g) * HD;
            float* op1 = op0 + 8 * HD;
            #pragma unroll
            for (int nt = 0; nt < 4; ++nt) {
                const int d = wn * 32 + nt * 8 + tig * 2;
                *(float2*)(op0 + d) = make_float2(o[nt][0] * li0, o[nt][1] * li0);
                *(float2*)(op1 + d) = make_float2(o[nt][2] * li1, o[nt][3] * li1);
            }
        }
        __syncthreads();   // before subt=1 reuses Q/stats/smem
    }
}

// ---------------------------------------------------------------------------
extern "C" void kernel_launch(void* const* d_in, const int* in_sizes, int n_in,
                              void* d_out, int out_size)
{
    const float* X  = (const float*)d_in[0];
    const float* Wq = (const float*)d_in[1];
    const float* bq = (const float*)d_in[2];
    const float* Wk = (const float*)d_in[3];
    const float* bk = (const float*)d_in[4];
    const float* Wv = (const float*)d_in[5];
    const float* bv = (const float*)d_in[6];
    float* out = (float*)d_out;

    prep_w<<<dim3(16, 3), 256>>>(Wq, Wk, Wv);

    cudaFuncSetAttribute(qkv_mma, cudaFuncAttributeMaxDynamicSharedMemorySize,
                         QSM_TOTAL);
    qkv_mma<<<dim3(64, 3), 256, QSM_TOTAL>>>(X, bq, bk, bv);

    cudaFuncSetAttribute(attn4, cudaFuncAttributeMaxDynamicSharedMemorySize,
                         ASM_TOTAL);
    attn4<<<dim3(32, 4), 256, ASM_TOTAL>>>(out);
}